// round 12
// baseline (speedup 1.0000x reference)
#include <cuda_runtime.h>
#include <cstdint>

// MMI softmax loss — collapsed gather form, single launch, 32 single-warp
// blocks, 2 d-values per thread (halves same-address atomic arrivals and
// CTA-dispatch count vs the 64-block variant; doubles per-thread MLP).
//
//   out = -(1/2048) * sum_d  emb[d, t_d] / (sum_{j=1..4} emb[d + j*2048, t_d])
//
// Handoff (empirical best from R7): leader publishes its f32 partial with
// st.global.cg (L1-bypassing) and arrives on a gpu-scope acq_rel counter
// (no fences -> no CCTL.IVALL). The LAST arriving warp alone folds the 32
// partials in a fixed shuffle tree (bit-deterministic), writes the scalar,
// and re-arms the counter for graph replay.

#define DIM   2048
#define NCLS  32000
#define NBLK  32
#define TPB   32
#define DPT   2     // d-values per thread; NBLK*TPB*DPT == DIM

__device__ float        g_partial[NBLK];
__device__ unsigned int g_count = 0;   // always left at 0 by the last warp

__global__ void __launch_bounds__(TPB, 1)
mmi_fused_kernel(const float* __restrict__ emb,
                 const int* __restrict__ tgt,
                 float* __restrict__ out) {
    const int lane = threadIdx.x;
    const int dA = blockIdx.x * TPB + lane;          // 0..1023
    const int dB = dA + NBLK * TPB;                  // 1024..2047

    // issue both target loads first; 32-bit row offsets (max 10239*32000 =
    // 3.28e8 < 2^31) computed under their latency
    const int tA = __ldg(&tgt[dA]);
    const int tB = __ldg(&tgt[dB]);

    const unsigned a0 = (unsigned)dA * (unsigned)NCLS;
    const unsigned b0 = (unsigned)dB * (unsigned)NCLS;
    const unsigned STEP = (unsigned)DIM * (unsigned)NCLS;

    // 10 independent gathers (MLP=10 per thread; latency overlapped)
    const float exA = __ldg(emb + (size_t)(a0 + 0 * STEP + (unsigned)tA));
    const float a1  = __ldg(emb + (size_t)(a0 + 1 * STEP + (unsigned)tA));
    const float a2  = __ldg(emb + (size_t)(a0 + 2 * STEP + (unsigned)tA));
    const float a3  = __ldg(emb + (size_t)(a0 + 3 * STEP + (unsigned)tA));
    const float a4  = __ldg(emb + (size_t)(a0 + 4 * STEP + (unsigned)tA));
    const float exB = __ldg(emb + (size_t)(b0 + 0 * STEP + (unsigned)tB));
    const float b1  = __ldg(emb + (size_t)(b0 + 1 * STEP + (unsigned)tB));
    const float b2  = __ldg(emb + (size_t)(b0 + 2 * STEP + (unsigned)tB));
    const float b3  = __ldg(emb + (size_t)(b0 + 3 * STEP + (unsigned)tB));
    const float b4  = __ldg(emb + (size_t)(b0 + 4 * STEP + (unsigned)tB));

    // fast divides (MUFU.RCP + mul, 2^-22 rel err — far under 1e-3 budget)
    float v = __fdividef(exA, ((a1 + a2) + a3) + a4)
            + __fdividef(exB, ((b1 + b2) + b3) + b4);

    // intra-warp reduce (fixed tree)
    #pragma unroll
    for (int o = 16; o; o >>= 1)
        v += __shfl_xor_sync(0xffffffffu, v, o);

    // Leader: publish partial to L2, arrive with gpu-scope acq_rel atomic.
    unsigned prev = 0;
    if (lane == 0) {
        asm volatile(
            "st.global.cg.f32 [%1], %2;\n\t"
            "atom.acq_rel.gpu.global.add.u32 %0, [%3], 1;\n\t"
            : "=r"(prev)
            : "l"(&g_partial[blockIdx.x]), "f"(v), "l"(&g_count)
            : "memory");
    }
    const bool is_last =
        (__shfl_sync(0xffffffffu, prev, 0) == (unsigned)(NBLK - 1));

    if (is_last) {
        // only ONE block runs this tail: fold 32 partials, fixed order
        float p;
        asm volatile("ld.acquire.gpu.global.f32 %0, [%1];"
                     : "=f"(p) : "l"(&g_partial[lane]) : "memory");
        #pragma unroll
        for (int o = 16; o; o >>= 1)
            p += __shfl_xor_sync(0xffffffffu, p, o);
        if (lane == 0) {
            *out = -(p / (float)DIM);
            g_count = 0;   // re-arm; visible at kernel boundary before replay
        }
    }
}

extern "C" void kernel_launch(void* const* d_in, const int* in_sizes, int n_in,
                              void* d_out, int out_size) {
    const float* emb = (const float*)d_in[0];   // embeddings [10240, 32000] f32
    const int*   tgt = (const int*)d_in[1];     // targets [2048] i32

    mmi_fused_kernel<<<NBLK, TPB>>>(emb, tgt, (float*)d_out);
}

// round 13
// speedup vs baseline: 1.0337x; 1.0337x over previous
#include <cuda_runtime.h>
#include <cstdint>

// MMI softmax loss — collapsed gather form, single launch, 32 single-warp
// blocks, 2 d-values per thread (halves same-address atomic arrivals and
// CTA-dispatch count vs the 64-block variant; doubles per-thread MLP).
//
//   out = -(1/2048) * sum_d  emb[d, t_d] / (sum_{j=1..4} emb[d + j*2048, t_d])
//
// Handoff (empirical best from R7): leader publishes its f32 partial with
// st.global.cg (L1-bypassing) and arrives on a gpu-scope acq_rel counter
// (no fences -> no CCTL.IVALL). The LAST arriving warp alone folds the 32
// partials in a fixed shuffle tree (bit-deterministic), writes the scalar,
// and re-arms the counter for graph replay.

#define DIM   2048
#define NCLS  32000
#define NBLK  32
#define TPB   32
#define DPT   2     // d-values per thread; NBLK*TPB*DPT == DIM

__device__ float        g_partial[NBLK];
__device__ unsigned int g_count = 0;   // always left at 0 by the last warp

__global__ void __launch_bounds__(TPB, 1)
mmi_fused_kernel(const float* __restrict__ emb,
                 const int* __restrict__ tgt,
                 float* __restrict__ out) {
    const int lane = threadIdx.x;
    const int dA = blockIdx.x * TPB + lane;          // 0..1023
    const int dB = dA + NBLK * TPB;                  // 1024..2047

    // issue both target loads first; 32-bit row offsets (max 10239*32000 =
    // 3.28e8 < 2^31) computed under their latency
    const int tA = __ldg(&tgt[dA]);
    const int tB = __ldg(&tgt[dB]);

    const unsigned a0 = (unsigned)dA * (unsigned)NCLS;
    const unsigned b0 = (unsigned)dB * (unsigned)NCLS;
    const unsigned STEP = (unsigned)DIM * (unsigned)NCLS;

    // 10 independent gathers (MLP=10 per thread; latency overlapped)
    const float exA = __ldg(emb + (size_t)(a0 + 0 * STEP + (unsigned)tA));
    const float a1  = __ldg(emb + (size_t)(a0 + 1 * STEP + (unsigned)tA));
    const float a2  = __ldg(emb + (size_t)(a0 + 2 * STEP + (unsigned)tA));
    const float a3  = __ldg(emb + (size_t)(a0 + 3 * STEP + (unsigned)tA));
    const float a4  = __ldg(emb + (size_t)(a0 + 4 * STEP + (unsigned)tA));
    const float exB = __ldg(emb + (size_t)(b0 + 0 * STEP + (unsigned)tB));
    const float b1  = __ldg(emb + (size_t)(b0 + 1 * STEP + (unsigned)tB));
    const float b2  = __ldg(emb + (size_t)(b0 + 2 * STEP + (unsigned)tB));
    const float b3  = __ldg(emb + (size_t)(b0 + 3 * STEP + (unsigned)tB));
    const float b4  = __ldg(emb + (size_t)(b0 + 4 * STEP + (unsigned)tB));

    // fast divides (MUFU.RCP + mul, 2^-22 rel err — far under 1e-3 budget)
    float v = __fdividef(exA, ((a1 + a2) + a3) + a4)
            + __fdividef(exB, ((b1 + b2) + b3) + b4);

    // intra-warp reduce (fixed tree)
    #pragma unroll
    for (int o = 16; o; o >>= 1)
        v += __shfl_xor_sync(0xffffffffu, v, o);

    // Leader: publish partial to L2, arrive with gpu-scope acq_rel atomic.
    unsigned prev = 0;
    if (lane == 0) {
        asm volatile(
            "st.global.cg.f32 [%1], %2;\n\t"
            "atom.acq_rel.gpu.global.add.u32 %0, [%3], 1;\n\t"
            : "=r"(prev)
            : "l"(&g_partial[blockIdx.x]), "f"(v), "l"(&g_count)
            : "memory");
    }
    const bool is_last =
        (__shfl_sync(0xffffffffu, prev, 0) == (unsigned)(NBLK - 1));

    if (is_last) {
        // only ONE block runs this tail: fold 32 partials, fixed order
        float p;
        asm volatile("ld.acquire.gpu.global.f32 %0, [%1];"
                     : "=f"(p) : "l"(&g_partial[lane]) : "memory");
        #pragma unroll
        for (int o = 16; o; o >>= 1)
            p += __shfl_xor_sync(0xffffffffu, p, o);
        if (lane == 0) {
            *out = -(p / (float)DIM);
            g_count = 0;   // re-arm; visible at kernel boundary before replay
        }
    }
}

extern "C" void kernel_launch(void* const* d_in, const int* in_sizes, int n_in,
                              void* d_out, int out_size) {
    const float* emb = (const float*)d_in[0];   // embeddings [10240, 32000] f32
    const int*   tgt = (const int*)d_in[1];     // targets [2048] i32

    mmi_fused_kernel<<<NBLK, TPB>>>(emb, tgt, (float*)d_out);
}